// round 2
// baseline (speedup 1.0000x reference)
#include <cuda_runtime.h>
#include <math.h>

#define T_STEPS 256
#define B_SZ    1024
#define Y_DIM   32
#define H_DIM   1024
#define R_DIM   512
#define R3      (3 * R_DIM)

// ---------------- scratch (device globals: no allocation allowed) ----------------
__device__ float  g_h0[B_SZ * R_DIM];
__device__ float  g_h1[B_SZ * R_DIM];
__device__ float  g_d1[B_SZ * H_DIM];
__device__ float  g_d2[B_SZ * H_DIM];
__device__ float  g_GI[B_SZ * R3];
__device__ float  g_GH[B_SZ * R3];
__device__ double g_nll;
__device__ unsigned int g_bar;   // zero-initialized; reset by finalize kernel each run

struct Smem {
    float As[16][64];
    float Ws[16][64];
    float Cs[64][65];
    float wsum[8];
};

// ---------------- grid-wide barrier (all blocks resident by construction) ----------------
__device__ __forceinline__ void grid_sync(unsigned int target) {
    __threadfence();          // release: make this thread's writes visible device-wide
    __syncthreads();          // order all block threads' fences before the arrive
    if (threadIdx.x == 0) {
        atomicAdd(&g_bar, 1u);
        while (*((volatile unsigned int*)&g_bar) < target) { __nanosleep(64); }
        __threadfence();      // acquire
    }
    __syncthreads();
}

// ---------------- 64x64 GEMM tile: C[bm:+64, bn:+64] = act(A@W^T + bias) ----------------
// A row-major [M,K], W row-major [N,K], C row-major [M,N]. K multiple of 16.
__device__ __forceinline__ void gemm_tile(float* __restrict__ C,
                                          const float* __restrict__ A,
                                          const float* __restrict__ W,
                                          const float* __restrict__ bias,
                                          int N, int K, int bm, int bn, int act,
                                          Smem* sm) {
    const int tid = threadIdx.x;
    const int tx = tid & 15, ty = tid >> 4;
    const int lr = tid >> 2;            // 0..63
    const int lk = (tid & 3) << 2;      // 0,4,8,12

    const float* Ap = A + (size_t)(bm + lr) * K + lk;
    const float* Wp = W + (size_t)(bn + lr) * K + lk;

    float acc[4][4];
#pragma unroll
    for (int i = 0; i < 4; i++)
#pragma unroll
        for (int j = 0; j < 4; j++) acc[i][j] = 0.0f;

    for (int k0 = 0; k0 < K; k0 += 16) {
        float4 av = *(const float4*)(Ap + k0);
        float4 wv = *(const float4*)(Wp + k0);
        sm->As[lk + 0][lr] = av.x; sm->As[lk + 1][lr] = av.y;
        sm->As[lk + 2][lr] = av.z; sm->As[lk + 3][lr] = av.w;
        sm->Ws[lk + 0][lr] = wv.x; sm->Ws[lk + 1][lr] = wv.y;
        sm->Ws[lk + 2][lr] = wv.z; sm->Ws[lk + 3][lr] = wv.w;
        __syncthreads();
#pragma unroll
        for (int k = 0; k < 16; k++) {
            float4 a = *(const float4*)&sm->As[k][ty << 2];
            float4 b = *(const float4*)&sm->Ws[k][tx << 2];
            float ar[4] = {a.x, a.y, a.z, a.w};
            float br[4] = {b.x, b.y, b.z, b.w};
#pragma unroll
            for (int i = 0; i < 4; i++)
#pragma unroll
                for (int j = 0; j < 4; j++) acc[i][j] += ar[i] * br[j];
        }
        __syncthreads();
    }

    float4 bv = *(const float4*)&bias[bn + (tx << 2)];
    float bj[4] = {bv.x, bv.y, bv.z, bv.w};
#pragma unroll
    for (int i = 0; i < 4; i++) {
        float4 o;
        o.x = acc[i][0] + bj[0];
        o.y = acc[i][1] + bj[1];
        o.z = acc[i][2] + bj[2];
        o.w = acc[i][3] + bj[3];
        if (act) {
            o.x = fmaxf(o.x, 0.0f); o.y = fmaxf(o.y, 0.0f);
            o.z = fmaxf(o.z, 0.0f); o.w = fmaxf(o.w, 0.0f);
        }
        *(float4*)(C + (size_t)(bm + (ty << 2) + i) * N + bn + (tx << 2)) = o;
    }
}

// ---------------- fused heads + NLL for 64 batch rows ----------------
__device__ __forceinline__ void heads_tile(int bm,
                                           const float* __restrict__ D,
                                           const float* __restrict__ mw,
                                           const float* __restrict__ mb,
                                           const float* __restrict__ sw,
                                           const float* __restrict__ sb,
                                           const float* __restrict__ yt,
                                           Smem* sm) {
    const int tid = threadIdx.x;
    const int tx = tid & 15, ty = tid >> 4;
    const int lr = tid >> 2;
    const int lk = (tid & 3) << 2;
    const int K = H_DIM;

    const float* Ap = D + (size_t)(bm + lr) * K + lk;
    const float* Wrow = (lr < 32) ? (mw + (size_t)lr * K) : (sw + (size_t)(lr - 32) * K);

    float acc[4][4];
#pragma unroll
    for (int i = 0; i < 4; i++)
#pragma unroll
        for (int j = 0; j < 4; j++) acc[i][j] = 0.0f;

    for (int k0 = 0; k0 < K; k0 += 16) {
        float4 av = *(const float4*)(Ap + k0);
        float4 wv = *(const float4*)(Wrow + lk + k0);
        sm->As[lk + 0][lr] = av.x; sm->As[lk + 1][lr] = av.y;
        sm->As[lk + 2][lr] = av.z; sm->As[lk + 3][lr] = av.w;
        sm->Ws[lk + 0][lr] = wv.x; sm->Ws[lk + 1][lr] = wv.y;
        sm->Ws[lk + 2][lr] = wv.z; sm->Ws[lk + 3][lr] = wv.w;
        __syncthreads();
#pragma unroll
        for (int k = 0; k < 16; k++) {
            float4 a = *(const float4*)&sm->As[k][ty << 2];
            float4 b = *(const float4*)&sm->Ws[k][tx << 2];
            float ar[4] = {a.x, a.y, a.z, a.w};
            float br[4] = {b.x, b.y, b.z, b.w};
#pragma unroll
            for (int i = 0; i < 4; i++)
#pragma unroll
                for (int j = 0; j < 4; j++) acc[i][j] += ar[i] * br[j];
        }
        __syncthreads();
    }

#pragma unroll
    for (int i = 0; i < 4; i++)
#pragma unroll
        for (int j = 0; j < 4; j++) {
            int c = (tx << 2) + j;
            float bb = (c < 32) ? mb[c] : sb[c - 32];
            sm->Cs[(ty << 2) + i][c] = acc[i][j] + bb;
        }
    __syncthreads();

    const float LOG2PI = 1.8378770664093453f;
    float local = 0.0f;
    for (int idx = tid; idx < 64 * 32; idx += 256) {
        int b = idx >> 5, yc = idx & 31;
        float mean = sm->Cs[b][yc];
        float s = sm->Cs[b][yc + 32];
        float std = (s > 15.0f) ? s : log1pf(expf(s));
        float diff = yt[(size_t)(bm + b) * Y_DIM + yc] - mean;
        local += diff * diff / (std * std) + 2.0f * logf(std) + LOG2PI;
    }
#pragma unroll
    for (int o = 16; o > 0; o >>= 1) local += __shfl_xor_sync(0xffffffffu, local, o);
    if ((tid & 31) == 0) sm->wsum[tid >> 5] = local;
    __syncthreads();
    if (tid == 0) {
        float s = 0.0f;
#pragma unroll
        for (int w = 0; w < 8; w++) s += sm->wsum[w];
        atomicAdd(&g_nll, (double)(0.5f * s));
    }
    __syncthreads();
}

// ---------------- GRU gate chunk: 256 consecutive elements of h ----------------
__device__ __forceinline__ void gates_chunk(float* __restrict__ h, int chunk) {
    int i = chunk * 256 + threadIdx.x;
    int b = i >> 9;                 // / R_DIM
    int n = i & (R_DIM - 1);
    size_t base = (size_t)b * R3 + n;
    float gir = g_GI[base], giz = g_GI[base + R_DIM], gin = g_GI[base + 2 * R_DIM];
    float ghr = g_GH[base], ghz = g_GH[base + R_DIM], ghn = g_GH[base + 2 * R_DIM];
    float r = 1.0f / (1.0f + expf(-(gir + ghr)));
    float z = 1.0f / (1.0f + expf(-(giz + ghz)));
    float nn = tanhf(gin + r * ghn);
    h[i] = (1.0f - z) * nn + z * h[i];
}

// ---------------- the whole model as one persistent kernel ----------------
__global__ __launch_bounds__(256) void rnn_persistent(
    const float* __restrict__ y,
    const float* __restrict__ dec_w1, const float* __restrict__ dec_b1,
    const float* __restrict__ dec_w2, const float* __restrict__ dec_b2,
    const float* __restrict__ mean_w, const float* __restrict__ mean_b,
    const float* __restrict__ std_w,  const float* __restrict__ std_b,
    const float* __restrict__ wih0,   const float* __restrict__ whh0,
    const float* __restrict__ bih0,   const float* __restrict__ bhh0,
    const float* __restrict__ wih1,   const float* __restrict__ whh1,
    const float* __restrict__ bih1,   const float* __restrict__ bhh1) {
    __shared__ Smem sm;
    const int nb = gridDim.x;
    unsigned int gen = 0;

    // init h0, h1, nll
    for (int i = blockIdx.x * 256 + threadIdx.x; i < B_SZ * R_DIM; i += nb * 256) {
        g_h0[i] = 0.0f; g_h1[i] = 0.0f;
    }
    if (blockIdx.x == 0 && threadIdx.x == 0) g_nll = 0.0;
    gen++; grid_sync(gen * nb);

    for (int t = 0; t < T_STEPS; t++) {
        const float* yt = y + (size_t)t * B_SZ * Y_DIM;

        // Phase A: dec1 (256) | GI0 (384) | GH0 (384)
        for (int w = blockIdx.x; w < 1024; w += nb) {
            if (w < 256) {
                gemm_tile(g_d1, g_h1, dec_w1, dec_b1, H_DIM, R_DIM,
                          (w >> 4) << 6, (w & 15) << 6, 1, &sm);
            } else if (w < 640) {
                int u = w - 256;
                gemm_tile(g_GI, yt, wih0, bih0, R3, Y_DIM,
                          (u / 24) << 6, (u % 24) << 6, 0, &sm);
            } else {
                int u = w - 640;
                gemm_tile(g_GH, g_h0, whh0, bhh0, R3, R_DIM,
                          (u / 24) << 6, (u % 24) << 6, 0, &sm);
            }
        }
        gen++; grid_sync(gen * nb);

        // Phase B: dec2 (256 tiles) | gates0 (2048 chunks -> h0)
        for (int w = blockIdx.x; w < 256 + 2048; w += nb) {
            if (w < 256) {
                gemm_tile(g_d2, g_d1, dec_w2, dec_b2, H_DIM, H_DIM,
                          (w >> 4) << 6, (w & 15) << 6, 1, &sm);
            } else {
                gates_chunk(g_h0, w - 256);
            }
        }
        gen++; grid_sync(gen * nb);

        // Phase C: heads+NLL (16) | GI1 (384) | GH1 (384)
        for (int w = blockIdx.x; w < 784; w += nb) {
            if (w < 16) {
                heads_tile(w << 6, g_d2, mean_w, mean_b, std_w, std_b, yt, &sm);
            } else if (w < 400) {
                int u = w - 16;
                gemm_tile(g_GI, g_h0, wih1, bih1, R3, R_DIM,
                          (u / 24) << 6, (u % 24) << 6, 0, &sm);
            } else {
                int u = w - 400;
                gemm_tile(g_GH, g_h1, whh1, bhh1, R3, R_DIM,
                          (u / 24) << 6, (u % 24) << 6, 0, &sm);
            }
        }
        gen++; grid_sync(gen * nb);

        // Phase D: gates1 (2048 chunks -> h1)
        for (int w = blockIdx.x; w < 2048; w += nb) gates_chunk(g_h1, w);
        if (t != T_STEPS - 1) { gen++; grid_sync(gen * nb); }
        // last step: kernel exit is the barrier
    }
}

// finalize in a separate launch: reads g_nll after the persistent kernel fully
// drains, and resets the barrier counter for the next replay (doing the reset
// inside the main kernel races with blocks still spinning on the last barrier).
__global__ void finalize_kernel(float* out) {
    out[0] = (float)g_nll;
    g_bar = 0u;
}

extern "C" void kernel_launch(void* const* d_in, const int* in_sizes, int n_in,
                              void* d_out, int out_size) {
    const float* y      = (const float*)d_in[0];
    const float* dec_w1 = (const float*)d_in[1];
    const float* dec_b1 = (const float*)d_in[2];
    const float* dec_w2 = (const float*)d_in[3];
    const float* dec_b2 = (const float*)d_in[4];
    const float* mean_w = (const float*)d_in[5];
    const float* mean_b = (const float*)d_in[6];
    const float* std_w  = (const float*)d_in[7];
    const float* std_b  = (const float*)d_in[8];
    const float* wih0   = (const float*)d_in[9];
    const float* whh0   = (const float*)d_in[10];
    const float* bih0   = (const float*)d_in[11];
    const float* bhh0   = (const float*)d_in[12];
    const float* wih1   = (const float*)d_in[13];
    const float* whh1   = (const float*)d_in[14];
    const float* bih1   = (const float*)d_in[15];
    const float* bhh1   = (const float*)d_in[16];

    // size the grid so every block is resident (required for the grid barrier)
    int dev = 0, nsm = 0, bpm = 0;
    cudaGetDevice(&dev);
    cudaDeviceGetAttribute(&nsm, cudaDevAttrMultiProcessorCount, dev);
    cudaOccupancyMaxActiveBlocksPerMultiprocessor(&bpm, rnn_persistent, 256, 0);
    if (bpm < 1) bpm = 1;
    int grid = nsm * bpm;
    if (grid > 1024) grid = 1024;   // no benefit beyond max phase tile count

    rnn_persistent<<<grid, 256>>>(y, dec_w1, dec_b1, dec_w2, dec_b2,
                                  mean_w, mean_b, std_w, std_b,
                                  wih0, whh0, bih0, bhh0,
                                  wih1, whh1, bih1, bhh1);
    finalize_kernel<<<1, 1>>>((float*)d_out);
}